// round 13
// baseline (speedup 1.0000x reference)
#include <cuda_runtime.h>
#include <cuda_fp16.h>
#include <mma.h>

using namespace nvcuda;

#define NN 100000
#define NE 800000
#define HC 512
#define IND 64
#define SCAN_B 1024
#define NBLK ((NN + SCAN_B - 1) / SCAN_B)   // 98

// ---------------- device scratch (no allocations allowed) ----------------
__device__ __half g_xl[(size_t)NN * HC];     // 102.4 MB
__device__ __half g_xr[(size_t)NN * HC];     // 102.4 MB
__device__ __half g_xh[(size_t)NN * IND];    // x in fp16, 12.8 MB
__device__ __half g_wh[2][IND * HC];         // W_l, W_r fp16
__device__ int    g_count[NN];
__device__ int    g_off[NN + 1];
__device__ int    g_cursor[NN];
__device__ int    g_srcs[NE];
__device__ int    g_bsum[NBLK];

struct U8 { unsigned int r[8]; };

// ---------------- cache-policy load/store helpers (32B, v8.b32) ----------------
__device__ __forceinline__ U8 ldg256_evict_last(const void* p) {
    U8 v;
    asm("ld.global.nc.L2::evict_last.v8.b32 {%0,%1,%2,%3,%4,%5,%6,%7}, [%8];"
        : "=r"(v.r[0]), "=r"(v.r[1]), "=r"(v.r[2]), "=r"(v.r[3]),
          "=r"(v.r[4]), "=r"(v.r[5]), "=r"(v.r[6]), "=r"(v.r[7]) : "l"(p));
    return v;
}
__device__ __forceinline__ U8 ldg256_evict_first(const void* p) {
    U8 v;
    asm("ld.global.nc.L2::evict_first.v8.b32 {%0,%1,%2,%3,%4,%5,%6,%7}, [%8];"
        : "=r"(v.r[0]), "=r"(v.r[1]), "=r"(v.r[2]), "=r"(v.r[3]),
          "=r"(v.r[4]), "=r"(v.r[5]), "=r"(v.r[6]), "=r"(v.r[7]) : "l"(p));
    return v;
}
__device__ __forceinline__ void stg_streaming(void* p, float4 v) {
    asm volatile("st.global.cs.v4.f32 [%0], {%1,%2,%3,%4};"
                 :: "l"(p), "f"(v.x), "f"(v.y), "f"(v.z), "f"(v.w));
}
__device__ __forceinline__ void stg_streaming_u4(void* p, uint4 v) {
    asm volatile("st.global.cs.v4.u32 [%0], {%1,%2,%3,%4};"
                 :: "l"(p), "r"(v.x), "r"(v.y), "r"(v.z), "r"(v.w));
}

// ---------------- fp32 -> fp16 conversions (+ fused count zeroing) ----------------
__global__ void convert_x_kernel(const float* __restrict__ x) {
    int i = blockIdx.x * blockDim.x + threadIdx.x;
    if (i < NN * IND) g_xh[i] = __float2half(x[i]);
    if (i < NN) g_count[i] = 0;
}
__global__ void convert_w_kernel(const float* __restrict__ Wl,
                                 const float* __restrict__ Wr) {
    int i = blockIdx.x * blockDim.x + threadIdx.x;
    if (i < IND * HC) {
        g_wh[0][i] = __float2half(Wl[i]);
        g_wh[1][i] = __float2half(Wr[i]);
    }
}

// ---------------- fused HMMA GEMM: xl AND xr in one kernel ----------------
#define A_LD 72
#define B_LD 72
#define C_LD 72

__global__ __launch_bounds__(256) void gemm2_kernel() {
    __shared__ __align__(16) __half As[128 * A_LD];    // 18432 B (later reused as Cs)
    __shared__ __align__(16) __half Bs[2][IND * B_LD]; // 2 x 9216 B

    const int rb  = blockIdx.x * 128;
    const int cb  = blockIdx.y * 64;
    const int tid = threadIdx.x;
    const int wid = tid >> 5;
    const int wr  = (wid >> 1) * 32;
    const int wc  = (wid & 1) * 32;

#pragma unroll
    for (int i = 0; i < 4; i++) {
        int idx = tid + i * 256;
        int r = idx >> 3, c8 = idx & 7;
        uint4 v = make_uint4(0, 0, 0, 0);
        if (rb + r < NN)
            v = *(const uint4*)(g_xh + (size_t)(rb + r) * IND + c8 * 8);
        *(uint4*)(As + r * A_LD + c8 * 8) = v;
    }
#pragma unroll
    for (int i = 0; i < 4; i++) {
        int idx = tid + i * 256;
        int m = idx >> 9;
        int r = (idx >> 3) & 63, c8 = idx & 7;
        uint4 v = *(const uint4*)(g_wh[m] + (size_t)r * HC + cb + c8 * 8);
        *(uint4*)(Bs[m] + r * B_LD + c8 * 8) = v;
    }
    __syncthreads();

    wmma::fragment<wmma::accumulator, 16, 16, 16, float> acc[2][2][2];
#pragma unroll
    for (int m = 0; m < 2; m++)
#pragma unroll
        for (int i = 0; i < 2; i++)
#pragma unroll
            for (int j = 0; j < 2; j++) wmma::fill_fragment(acc[m][i][j], 0.0f);

#pragma unroll
    for (int k = 0; k < 4; k++) {
        wmma::fragment<wmma::matrix_a, 16, 16, 16, __half, wmma::row_major> a0, a1;
        wmma::load_matrix_sync(a0, As + (wr + 0)  * A_LD + k * 16, A_LD);
        wmma::load_matrix_sync(a1, As + (wr + 16) * A_LD + k * 16, A_LD);
#pragma unroll
        for (int m = 0; m < 2; m++) {
            wmma::fragment<wmma::matrix_b, 16, 16, 16, __half, wmma::row_major> b0, b1;
            wmma::load_matrix_sync(b0, Bs[m] + (k * 16) * B_LD + wc + 0,  B_LD);
            wmma::load_matrix_sync(b1, Bs[m] + (k * 16) * B_LD + wc + 16, B_LD);
            wmma::mma_sync(acc[m][0][0], a0, b0, acc[m][0][0]);
            wmma::mma_sync(acc[m][0][1], a0, b1, acc[m][0][1]);
            wmma::mma_sync(acc[m][1][0], a1, b0, acc[m][1][0]);
            wmma::mma_sync(acc[m][1][1], a1, b1, acc[m][1][1]);
        }
    }
    __syncthreads();

    __half* Cs = As;
#pragma unroll
    for (int m = 0; m < 2; m++) {
        __half* __restrict__ Y = m ? g_xr : g_xl;
#pragma unroll
        for (int i = 0; i < 2; i++)
#pragma unroll
            for (int j = 0; j < 2; j++) {
                wmma::fragment<wmma::accumulator, 16, 16, 16, __half> h;
#pragma unroll
                for (int t = 0; t < h.num_elements; t++)
                    h.x[t] = __float2half(acc[m][i][j].x[t]);
                wmma::store_matrix_sync(Cs + (wr + i * 16) * C_LD + wc + j * 16,
                                        h, C_LD, wmma::mem_row_major);
            }
        __syncthreads();
#pragma unroll
        for (int i = 0; i < 4; i++) {
            int idx = tid + i * 256;
            int r = idx >> 3, c8 = idx & 7;
            if (rb + r < NN) {
                uint4 v = *(const uint4*)(Cs + r * C_LD + c8 * 8);
                void* dst = Y + (size_t)(rb + r) * HC + cb + c8 * 8;
                if (m) stg_streaming_u4(dst, v);   // xr: read-once later
                else   *(uint4*)dst = v;           // xl: hot gather target
            }
        }
        __syncthreads();
    }
}

// ---------------- CSR build ----------------
__global__ void hist_kernel(const int* __restrict__ dst) {
    int e = blockIdx.x * blockDim.x + threadIdx.x;
    if (e < NE) atomicAdd(&g_count[dst[e]], 1);
}

__global__ __launch_bounds__(SCAN_B) void scan_block_kernel() {
    __shared__ int sm[SCAN_B];
    int i = blockIdx.x * SCAN_B + threadIdx.x;
    int v = (i < NN) ? g_count[i] : 0;
    sm[threadIdx.x] = v;
    __syncthreads();
    for (int off = 1; off < SCAN_B; off <<= 1) {
        int t = (threadIdx.x >= off) ? sm[threadIdx.x - off] : 0;
        __syncthreads();
        sm[threadIdx.x] += t;
        __syncthreads();
    }
    if (i < NN) g_off[i] = sm[threadIdx.x] - v;
    if (threadIdx.x == SCAN_B - 1) g_bsum[blockIdx.x] = sm[SCAN_B - 1];
}

__global__ void scan_sums_kernel() {
    __shared__ int sm[128];
    int t = threadIdx.x;
    int v = (t < NBLK) ? g_bsum[t] : 0;
    sm[t] = v;
    __syncthreads();
    for (int off = 1; off < 128; off <<= 1) {
        int u = (t >= off) ? sm[t - off] : 0;
        __syncthreads();
        sm[t] += u;
        __syncthreads();
    }
    if (t < NBLK) g_bsum[t] = sm[t] - v;
}

__global__ __launch_bounds__(SCAN_B) void scan_add_kernel() {
    int i = blockIdx.x * SCAN_B + threadIdx.x;
    if (i < NN) {
        int o = g_off[i] + g_bsum[blockIdx.x];
        g_off[i] = o;
        g_cursor[i] = o;
    }
    if (i == 0) g_off[NN] = NE;
}

__global__ void scatter_kernel(const int* __restrict__ src,
                               const int* __restrict__ dst) {
    int e = blockIdx.x * blockDim.x + threadIdx.x;
    if (e < NE) {
        int d = dst[e];
        int pos = atomicAdd(&g_cursor[d], 1);
        g_srcs[pos] = src[e];
    }
}

// ---------------- fused node kernel: online softmax + aggregate ----------------
// one warp per destination node; 16 features (fp16) per lane; head = lane>>2
// __launch_bounds__(256,3): cap regs ~85 -> 3 blocks/SM (24 warps) for latency hiding
__device__ __forceinline__ float2 h2f(unsigned int u) {
    __half2 h = *reinterpret_cast<__half2*>(&u);
    return __half22float2(h);
}

__global__ __launch_bounds__(256, 3) void node_kernel(const float* __restrict__ att,
                                                      const float* __restrict__ bias,
                                                      float* __restrict__ out) {
    int gw = (blockIdx.x * 256 + threadIdx.x) >> 5;
    int lane = threadIdx.x & 31;
    if (gw >= NN) return;
    const int base = lane * 16;

    U8 xu = ldg256_evict_first(g_xr + (size_t)gw * HC + base);
    float2 xr0 = h2f(xu.r[0]), xr1 = h2f(xu.r[1]), xr2 = h2f(xu.r[2]), xr3 = h2f(xu.r[3]);
    float2 xr4 = h2f(xu.r[4]), xr5 = h2f(xu.r[5]), xr6 = h2f(xu.r[6]), xr7 = h2f(xu.r[7]);

    float4 at0 = *(const float4*)(att + base + 0);
    float4 at1 = *(const float4*)(att + base + 4);
    float4 at2 = *(const float4*)(att + base + 8);
    float4 at3 = *(const float4*)(att + base + 12);

    int p0 = g_off[gw];
    int p1 = g_off[gw + 1];

    float acc[16];
#pragma unroll
    for (int t = 0; t < 16; t++) acc[t] = 0.f;
    float denom = 0.f;

    auto edge = [&](const U8& c) {
        float2 f0 = h2f(c.r[0]), f1 = h2f(c.r[1]), f2 = h2f(c.r[2]), f3 = h2f(c.r[3]);
        float2 f4 = h2f(c.r[4]), f5 = h2f(c.r[5]), f6 = h2f(c.r[6]), f7 = h2f(c.r[7]);
        float sA = 0.f, sB = 0.f;
#define TERM(cv, xv, av) { float s_ = (cv) + (xv); sA = fmaf((av), s_, sA); sB = fmaf((av), fabsf(s_), sB); }
        TERM(f0.x, xr0.x, at0.x) TERM(f0.y, xr0.y, at0.y) TERM(f1.x, xr1.x, at0.z) TERM(f1.y, xr1.y, at0.w)
        TERM(f2.x, xr2.x, at1.x) TERM(f2.y, xr2.y, at1.y) TERM(f3.x, xr3.x, at1.z) TERM(f3.y, xr3.y, at1.w)
        TERM(f4.x, xr4.x, at2.x) TERM(f4.y, xr4.y, at2.y) TERM(f5.x, xr5.x, at2.z) TERM(f5.y, xr5.y, at2.w)
        TERM(f6.x, xr6.x, at3.x) TERM(f6.y, xr6.y, at3.y) TERM(f7.x, xr7.x, at3.z) TERM(f7.y, xr7.y, at3.w)
#undef TERM
        float part = fmaf(0.6f, sA, 0.4f * sB);   // == sum att*leaky02(s)
        part += __shfl_xor_sync(0xffffffffu, part, 1);
        part += __shfl_xor_sync(0xffffffffu, part, 2);
        // max-free online softmax: |e| small, fp32 exp safe
        float ex = __expf(part);
        denom += ex;
        acc[0]  = fmaf(ex, f0.x, acc[0]);  acc[1]  = fmaf(ex, f0.y, acc[1]);
        acc[2]  = fmaf(ex, f1.x, acc[2]);  acc[3]  = fmaf(ex, f1.y, acc[3]);
        acc[4]  = fmaf(ex, f2.x, acc[4]);  acc[5]  = fmaf(ex, f2.y, acc[5]);
        acc[6]  = fmaf(ex, f3.x, acc[6]);  acc[7]  = fmaf(ex, f3.y, acc[7]);
        acc[8]  = fmaf(ex, f4.x, acc[8]);  acc[9]  = fmaf(ex, f4.y, acc[9]);
        acc[10] = fmaf(ex, f5.x, acc[10]); acc[11] = fmaf(ex, f5.y, acc[11]);
        acc[12] = fmaf(ex, f6.x, acc[12]); acc[13] = fmaf(ex, f6.y, acc[13]);
        acc[14] = fmaf(ex, f7.x, acc[14]); acc[15] = fmaf(ex, f7.y, acc[15]);
    };

    if (p0 < p1) {
        int last = p1 - 1;
        int pB = (p0 + 1 < p1) ? (p0 + 1) : last;
        U8 cA = ldg256_evict_last(g_xl + (size_t)__ldg(&g_srcs[p0]) * HC + base);
        U8 cB = ldg256_evict_last(g_xl + (size_t)__ldg(&g_srcs[pB]) * HC + base);

        for (int p = p0; p < p1; p += 2) {
            // L2 prefetch 4-5 edges ahead (no registers, no scoreboard)
            int w0 = (p + 4 <= last) ? (p + 4) : last;
            int w1 = (p + 5 <= last) ? (p + 5) : last;
            const __half* pf0 = g_xl + (size_t)__ldg(&g_srcs[w0]) * HC + base;
            const __half* pf1 = g_xl + (size_t)__ldg(&g_srcs[w1]) * HC + base;
            asm volatile("prefetch.global.L2 [%0];" :: "l"(pf0));
            asm volatile("prefetch.global.L2 [%0];" :: "l"(pf1));

            // register prefetch of the next pair
            int q0 = (p + 2 <= last) ? (p + 2) : last;
            int q1 = (p + 3 <= last) ? (p + 3) : last;
            U8 nA = ldg256_evict_last(g_xl + (size_t)__ldg(&g_srcs[q0]) * HC + base);
            U8 nB = ldg256_evict_last(g_xl + (size_t)__ldg(&g_srcs[q1]) * HC + base);

            edge(cA);
            if (p + 1 < p1) edge(cB);

            cA = nA;
            cB = nB;
        }
    }

    float inv = 1.0f / (denom + 1e-16f);
    float4 b0 = *(const float4*)(bias + base + 0);
    float4 b1 = *(const float4*)(bias + base + 4);
    float4 b2 = *(const float4*)(bias + base + 8);
    float4 b3 = *(const float4*)(bias + base + 12);
    float* op = out + (size_t)gw * HC + base;
    stg_streaming(op + 0,  make_float4(acc[0] * inv + b0.x,  acc[1] * inv + b0.y,
                                       acc[2] * inv + b0.z,  acc[3] * inv + b0.w));
    stg_streaming(op + 4,  make_float4(acc[4] * inv + b1.x,  acc[5] * inv + b1.y,
                                       acc[6] * inv + b1.z,  acc[7] * inv + b1.w));
    stg_streaming(op + 8,  make_float4(acc[8] * inv + b2.x,  acc[9] * inv + b2.y,
                                       acc[10] * inv + b2.z, acc[11] * inv + b2.w));
    stg_streaming(op + 12, make_float4(acc[12] * inv + b3.x, acc[13] * inv + b3.y,
                                       acc[14] * inv + b3.z, acc[15] * inv + b3.w));
}

// ---------------- launch ----------------
extern "C" void kernel_launch(void* const* d_in, const int* in_sizes, int n_in,
                              void* d_out, int out_size) {
    const float* x    = (const float*)d_in[0];
    const int*   ei   = (const int*)d_in[1];   // [2, NE] int32 (JAX x64 disabled)
    const float* W_l  = (const float*)d_in[2];
    const float* W_r  = (const float*)d_in[3];
    const float* att  = (const float*)d_in[4];
    const float* bias = (const float*)d_in[5];
    float*       out  = (float*)d_out;

    const int* src = ei;
    const int* dst = ei + NE;

    convert_x_kernel<<<(NN * IND + 255) / 256, 256>>>(x);
    convert_w_kernel<<<(IND * HC + 255) / 256, 256>>>(W_l, W_r);

    dim3 ggrid((NN + 127) / 128, HC / 64);
    gemm2_kernel<<<ggrid, 256>>>();

    hist_kernel<<<(NE + 255) / 256, 256>>>(dst);
    scan_block_kernel<<<NBLK, SCAN_B>>>();
    scan_sums_kernel<<<1, 128>>>();
    scan_add_kernel<<<NBLK, SCAN_B>>>();
    scatter_kernel<<<(NE + 255) / 256, 256>>>(src, dst);

    node_kernel<<<(NN * 32 + 255) / 256, 256>>>(att, bias, out);
}

// round 14
// speedup vs baseline: 1.1536x; 1.1536x over previous
#include <cuda_runtime.h>
#include <cuda_fp16.h>
#include <mma.h>

using namespace nvcuda;

#define NN 100000
#define NE 800000
#define HC 512
#define IND 64
#define SCAN_B 1024
#define NBLK ((NN + SCAN_B - 1) / SCAN_B)   // 98

// ---------------- device scratch (no allocations allowed) ----------------
__device__ __half g_xl[(size_t)NN * HC];     // 102.4 MB
__device__ __half g_xr[(size_t)NN * HC];     // 102.4 MB
__device__ __half g_xh[(size_t)NN * IND];    // x in fp16, 12.8 MB
__device__ __half g_wh[2][IND * HC];         // W_l, W_r fp16
__device__ int    g_count[NN];
__device__ int    g_off[NN + 1];
__device__ int    g_cursor[NN];
__device__ int    g_srcs[NE];
__device__ int    g_bsum[NBLK];

typedef unsigned long long u64;

// ---------------- cache-policy helpers ----------------
__device__ __forceinline__ u64 policy_evict_last() {
    u64 pol; asm("createpolicy.fractional.L2::evict_last.b64 %0, 1.0;" : "=l"(pol));
    return pol;
}
__device__ __forceinline__ u64 policy_evict_first() {
    u64 pol; asm("createpolicy.fractional.L2::evict_first.b64 %0, 1.0;" : "=l"(pol));
    return pol;
}
__device__ __forceinline__ uint4 ldg128_hint(const void* p, u64 pol) {
    uint4 v;
    asm("ld.global.nc.L2::cache_hint.v4.b32 {%0,%1,%2,%3}, [%4], %5;"
        : "=r"(v.x), "=r"(v.y), "=r"(v.z), "=r"(v.w) : "l"(p), "l"(pol));
    return v;
}
__device__ __forceinline__ void stg_streaming(void* p, float4 v) {
    asm volatile("st.global.cs.v4.f32 [%0], {%1,%2,%3,%4};"
                 :: "l"(p), "f"(v.x), "f"(v.y), "f"(v.z), "f"(v.w));
}
__device__ __forceinline__ void stg_streaming_u4(void* p, uint4 v) {
    asm volatile("st.global.cs.v4.u32 [%0], {%1,%2,%3,%4};"
                 :: "l"(p), "r"(v.x), "r"(v.y), "r"(v.z), "r"(v.w));
}

// ---------------- fp32 -> fp16 conversions (+ fused count zeroing) ----------------
__global__ void convert_x_kernel(const float* __restrict__ x) {
    int i = blockIdx.x * blockDim.x + threadIdx.x;
    if (i < NN * IND) g_xh[i] = __float2half(x[i]);
    if (i < NN) g_count[i] = 0;
}
__global__ void convert_w_kernel(const float* __restrict__ Wl,
                                 const float* __restrict__ Wr) {
    int i = blockIdx.x * blockDim.x + threadIdx.x;
    if (i < IND * HC) {
        g_wh[0][i] = __float2half(Wl[i]);
        g_wh[1][i] = __float2half(Wr[i]);
    }
}

// ---------------- fused HMMA GEMM: xl AND xr in one kernel (R6 proven) ----------------
#define A_LD 72
#define B_LD 72
#define C_LD 72

__global__ __launch_bounds__(256) void gemm2_kernel() {
    __shared__ __align__(16) __half As[128 * A_LD];    // 18432 B (later reused as Cs)
    __shared__ __align__(16) __half Bs[2][IND * B_LD]; // 2 x 9216 B

    const int rb  = blockIdx.x * 128;
    const int cb  = blockIdx.y * 64;
    const int tid = threadIdx.x;
    const int wid = tid >> 5;
    const int wr  = (wid >> 1) * 32;
    const int wc  = (wid & 1) * 32;

#pragma unroll
    for (int i = 0; i < 4; i++) {
        int idx = tid + i * 256;
        int r = idx >> 3, c8 = idx & 7;
        uint4 v = make_uint4(0, 0, 0, 0);
        if (rb + r < NN)
            v = *(const uint4*)(g_xh + (size_t)(rb + r) * IND + c8 * 8);
        *(uint4*)(As + r * A_LD + c8 * 8) = v;
    }
#pragma unroll
    for (int i = 0; i < 4; i++) {
        int idx = tid + i * 256;
        int m = idx >> 9;
        int r = (idx >> 3) & 63, c8 = idx & 7;
        uint4 v = *(const uint4*)(g_wh[m] + (size_t)r * HC + cb + c8 * 8);
        *(uint4*)(Bs[m] + r * B_LD + c8 * 8) = v;
    }
    __syncthreads();

    wmma::fragment<wmma::accumulator, 16, 16, 16, float> acc[2][2][2];
#pragma unroll
    for (int m = 0; m < 2; m++)
#pragma unroll
        for (int i = 0; i < 2; i++)
#pragma unroll
            for (int j = 0; j < 2; j++) wmma::fill_fragment(acc[m][i][j], 0.0f);

#pragma unroll
    for (int k = 0; k < 4; k++) {
        wmma::fragment<wmma::matrix_a, 16, 16, 16, __half, wmma::row_major> a0, a1;
        wmma::load_matrix_sync(a0, As + (wr + 0)  * A_LD + k * 16, A_LD);
        wmma::load_matrix_sync(a1, As + (wr + 16) * A_LD + k * 16, A_LD);
#pragma unroll
        for (int m = 0; m < 2; m++) {
            wmma::fragment<wmma::matrix_b, 16, 16, 16, __half, wmma::row_major> b0, b1;
            wmma::load_matrix_sync(b0, Bs[m] + (k * 16) * B_LD + wc + 0,  B_LD);
            wmma::load_matrix_sync(b1, Bs[m] + (k * 16) * B_LD + wc + 16, B_LD);
            wmma::mma_sync(acc[m][0][0], a0, b0, acc[m][0][0]);
            wmma::mma_sync(acc[m][0][1], a0, b1, acc[m][0][1]);
            wmma::mma_sync(acc[m][1][0], a1, b0, acc[m][1][0]);
            wmma::mma_sync(acc[m][1][1], a1, b1, acc[m][1][1]);
        }
    }
    __syncthreads();

    __half* Cs = As;
#pragma unroll
    for (int m = 0; m < 2; m++) {
        __half* __restrict__ Y = m ? g_xr : g_xl;
#pragma unroll
        for (int i = 0; i < 2; i++)
#pragma unroll
            for (int j = 0; j < 2; j++) {
                wmma::fragment<wmma::accumulator, 16, 16, 16, __half> h;
#pragma unroll
                for (int t = 0; t < h.num_elements; t++)
                    h.x[t] = __float2half(acc[m][i][j].x[t]);
                wmma::store_matrix_sync(Cs + (wr + i * 16) * C_LD + wc + j * 16,
                                        h, C_LD, wmma::mem_row_major);
            }
        __syncthreads();
#pragma unroll
        for (int i = 0; i < 4; i++) {
            int idx = tid + i * 256;
            int r = idx >> 3, c8 = idx & 7;
            if (rb + r < NN) {
                uint4 v = *(const uint4*)(Cs + r * C_LD + c8 * 8);
                void* dst = Y + (size_t)(rb + r) * HC + cb + c8 * 8;
                if (m) stg_streaming_u4(dst, v);   // xr: read-once later
                else   *(uint4*)dst = v;           // xl: hot gather target
            }
        }
        __syncthreads();
    }
}

// ---------------- CSR build ----------------
__global__ void hist_kernel(const int* __restrict__ dst) {
    int e = blockIdx.x * blockDim.x + threadIdx.x;
    if (e < NE) atomicAdd(&g_count[dst[e]], 1);
}

__global__ __launch_bounds__(SCAN_B) void scan_block_kernel() {
    __shared__ int sm[SCAN_B];
    int i = blockIdx.x * SCAN_B + threadIdx.x;
    int v = (i < NN) ? g_count[i] : 0;
    sm[threadIdx.x] = v;
    __syncthreads();
    for (int off = 1; off < SCAN_B; off <<= 1) {
        int t = (threadIdx.x >= off) ? sm[threadIdx.x - off] : 0;
        __syncthreads();
        sm[threadIdx.x] += t;
        __syncthreads();
    }
    if (i < NN) g_off[i] = sm[threadIdx.x] - v;
    if (threadIdx.x == SCAN_B - 1) g_bsum[blockIdx.x] = sm[SCAN_B - 1];
}

__global__ void scan_sums_kernel() {
    __shared__ int sm[128];
    int t = threadIdx.x;
    int v = (t < NBLK) ? g_bsum[t] : 0;
    sm[t] = v;
    __syncthreads();
    for (int off = 1; off < 128; off <<= 1) {
        int u = (t >= off) ? sm[t - off] : 0;
        __syncthreads();
        sm[t] += u;
        __syncthreads();
    }
    if (t < NBLK) g_bsum[t] = sm[t] - v;
}

__global__ __launch_bounds__(SCAN_B) void scan_add_kernel() {
    int i = blockIdx.x * SCAN_B + threadIdx.x;
    if (i < NN) {
        int o = g_off[i] + g_bsum[blockIdx.x];
        g_off[i] = o;
        g_cursor[i] = o;
    }
    if (i == 0) g_off[NN] = NE;
}

__global__ void scatter_kernel(const int* __restrict__ src,
                               const int* __restrict__ dst) {
    int e = blockIdx.x * blockDim.x + threadIdx.x;
    if (e < NE) {
        int d = dst[e];
        int pos = atomicAdd(&g_cursor[d], 1);
        g_srcs[pos] = src[e];
    }
}

// ---------------- fused node kernel: online softmax + aggregate ----------------
// TWO warps per destination node: warp-half h owns features [h*256, h*256+256)
// = 4 complete heads (8 feats/lane, head spans 8 lanes -> 3 shfl_xor reduce).
// Halved per-thread state (~60 regs) => 4 blocks/SM = 32 warps latency hiding.
__device__ __forceinline__ float2 h2f(unsigned int u) {
    __half2 h = *reinterpret_cast<__half2*>(&u);
    return __half22float2(h);
}

__global__ __launch_bounds__(256) void node_kernel(const float* __restrict__ att,
                                                   const float* __restrict__ bias,
                                                   float* __restrict__ out) {
    int gw = (blockIdx.x * 256 + threadIdx.x) >> 5;   // global warp id
    int node = gw >> 1;
    int half = gw & 1;
    int lane = threadIdx.x & 31;
    if (node >= NN) return;
    const int base = half * 256 + lane * 8;   // 8 features per lane

    const u64 polL = policy_evict_last();
    const u64 polF = policy_evict_first();

    uint4 xu = ldg128_hint(g_xr + (size_t)node * HC + base, polF);
    float2 xr0 = h2f(xu.x), xr1 = h2f(xu.y), xr2 = h2f(xu.z), xr3 = h2f(xu.w);

    float4 at0 = *(const float4*)(att + base + 0);
    float4 at1 = *(const float4*)(att + base + 4);

    int p0 = g_off[node];
    int p1 = g_off[node + 1];

    float acc[8];
#pragma unroll
    for (int t = 0; t < 8; t++) acc[t] = 0.f;
    float denom = 0.f;

    auto edge = [&](const uint4& c) {
        float2 f0 = h2f(c.x), f1 = h2f(c.y), f2 = h2f(c.z), f3 = h2f(c.w);
        float sA = 0.f, sB = 0.f;
#define TERM(cv, xv, av) { float s_ = (cv) + (xv); sA = fmaf((av), s_, sA); sB = fmaf((av), fabsf(s_), sB); }
        TERM(f0.x, xr0.x, at0.x) TERM(f0.y, xr0.y, at0.y)
        TERM(f1.x, xr1.x, at0.z) TERM(f1.y, xr1.y, at0.w)
        TERM(f2.x, xr2.x, at1.x) TERM(f2.y, xr2.y, at1.y)
        TERM(f3.x, xr3.x, at1.z) TERM(f3.y, xr3.y, at1.w)
#undef TERM
        float part = fmaf(0.6f, sA, 0.4f * sB);   // == sum att*leaky02(s), 8 feats
        // reduce over the 8 lanes of this head (head = 8 lanes @ 8 feats)
        part += __shfl_xor_sync(0xffffffffu, part, 1);
        part += __shfl_xor_sync(0xffffffffu, part, 2);
        part += __shfl_xor_sync(0xffffffffu, part, 4);
        // max-free online softmax: |e| small, fp32 exp safe
        float ex = __expf(part);
        denom += ex;
        acc[0] = fmaf(ex, f0.x, acc[0]); acc[1] = fmaf(ex, f0.y, acc[1]);
        acc[2] = fmaf(ex, f1.x, acc[2]); acc[3] = fmaf(ex, f1.y, acc[3]);
        acc[4] = fmaf(ex, f2.x, acc[4]); acc[5] = fmaf(ex, f2.y, acc[5]);
        acc[6] = fmaf(ex, f3.x, acc[6]); acc[7] = fmaf(ex, f3.y, acc[7]);
    };

    if (p0 < p1) {
        int last = p1 - 1;
        int pB = (p0 + 1 < p1) ? (p0 + 1) : last;
        uint4 cA = ldg128_hint(g_xl + (size_t)__ldg(&g_srcs[p0]) * HC + base, polL);
        uint4 cB = ldg128_hint(g_xl + (size_t)__ldg(&g_srcs[pB]) * HC + base, polL);

        for (int p = p0; p < p1; p += 2) {
            // L2 prefetch 4-5 edges ahead (no registers, no scoreboard)
            int w0 = (p + 4 <= last) ? (p + 4) : last;
            int w1 = (p + 5 <= last) ? (p + 5) : last;
            const __half* pf0 = g_xl + (size_t)__ldg(&g_srcs[w0]) * HC + base;
            const __half* pf1 = g_xl + (size_t)__ldg(&g_srcs[w1]) * HC + base;
            asm volatile("prefetch.global.L2 [%0];" :: "l"(pf0));
            asm volatile("prefetch.global.L2 [%0];" :: "l"(pf1));

            // register prefetch of the next pair
            int q0 = (p + 2 <= last) ? (p + 2) : last;
            int q1 = (p + 3 <= last) ? (p + 3) : last;
            uint4 nA = ldg128_hint(g_xl + (size_t)__ldg(&g_srcs[q0]) * HC + base, polL);
            uint4 nB = ldg128_hint(g_xl + (size_t)__ldg(&g_srcs[q1]) * HC + base, polL);

            edge(cA);
            if (p + 1 < p1) edge(cB);

            cA = nA;
            cB = nB;
        }
    }

    float inv = 1.0f / (denom + 1e-16f);
    float4 b0 = *(const float4*)(bias + base + 0);
    float4 b1 = *(const float4*)(bias + base + 4);
    float* op = out + (size_t)node * HC + base;
    stg_streaming(op + 0, make_float4(acc[0] * inv + b0.x, acc[1] * inv + b0.y,
                                      acc[2] * inv + b0.z, acc[3] * inv + b0.w));
    stg_streaming(op + 4, make_float4(acc[4] * inv + b1.x, acc[5] * inv + b1.y,
                                      acc[6] * inv + b1.z, acc[7] * inv + b1.w));
}

// ---------------- launch ----------------
extern "C" void kernel_launch(void* const* d_in, const int* in_sizes, int n_in,
                              void* d_out, int out_size) {
    const float* x    = (const float*)d_in[0];
    const int*   ei   = (const int*)d_in[1];   // [2, NE] int32 (JAX x64 disabled)
    const float* W_l  = (const float*)d_in[2];
    const float* W_r  = (const float*)d_in[3];
    const float* att  = (const float*)d_in[4];
    const float* bias = (const float*)d_in[5];
    float*       out  = (float*)d_out;

    const int* src = ei;
    const int* dst = ei + NE;

    convert_x_kernel<<<(NN * IND + 255) / 256, 256>>>(x);
    convert_w_kernel<<<(IND * HC + 255) / 256, 256>>>(W_l, W_r);

    dim3 ggrid((NN + 127) / 128, HC / 64);
    gemm2_kernel<<<ggrid, 256>>>();

    hist_kernel<<<(NE + 255) / 256, 256>>>(dst);
    scan_block_kernel<<<NBLK, SCAN_B>>>();
    scan_sums_kernel<<<1, 128>>>();
    scan_add_kernel<<<NBLK, SCAN_B>>>();
    scatter_kernel<<<(NE + 255) / 256, 256>>>(src, dst);

    // two warps per node
    node_kernel<<<(NN * 64 + 255) / 256, 256>>>(att, bias, out);
}

// round 15
// speedup vs baseline: 1.1831x; 1.0255x over previous
#include <cuda_runtime.h>
#include <cuda_fp16.h>
#include <mma.h>

using namespace nvcuda;

#define NN 100000
#define NE 800000
#define HC 512
#define IND 64
#define SCAN_B 1024
#define NBLK ((NN + SCAN_B - 1) / SCAN_B)   // 98

// ---------------- device scratch (no allocations allowed) ----------------
__device__ __half g_xl[(size_t)NN * HC];     // 102.4 MB
__device__ __half g_xr[(size_t)NN * HC];     // 102.4 MB
__device__ __half g_xh[(size_t)NN * IND];    // x in fp16, 12.8 MB
__device__ __half g_wh[2][IND * HC];         // W_l, W_r fp16
__device__ int    g_count[NN];
__device__ int    g_off[NN + 1];
__device__ int    g_cursor[NN];
__device__ int    g_srcs[NE];
__device__ int    g_bsum[NBLK];

typedef unsigned long long u64;

// ---------------- cache-policy helpers ----------------
__device__ __forceinline__ u64 policy_evict_last() {
    u64 pol; asm("createpolicy.fractional.L2::evict_last.b64 %0, 1.0;" : "=l"(pol));
    return pol;
}
__device__ __forceinline__ u64 policy_evict_first() {
    u64 pol; asm("createpolicy.fractional.L2::evict_first.b64 %0, 1.0;" : "=l"(pol));
    return pol;
}
__device__ __forceinline__ uint4 ldg128_hint(const void* p, u64 pol) {
    uint4 v;
    asm("ld.global.nc.L2::cache_hint.v4.b32 {%0,%1,%2,%3}, [%4], %5;"
        : "=r"(v.x), "=r"(v.y), "=r"(v.z), "=r"(v.w) : "l"(p), "l"(pol));
    return v;
}
__device__ __forceinline__ void stg_streaming(void* p, float4 v) {
    asm volatile("st.global.cs.v4.f32 [%0], {%1,%2,%3,%4};"
                 :: "l"(p), "f"(v.x), "f"(v.y), "f"(v.z), "f"(v.w));
}
__device__ __forceinline__ void stg_streaming_u4(void* p, uint4 v) {
    asm volatile("st.global.cs.v4.u32 [%0], {%1,%2,%3,%4};"
                 :: "l"(p), "r"(v.x), "r"(v.y), "r"(v.z), "r"(v.w));
}

// ---------------- fp32 -> fp16 conversions ----------------
__global__ void convert_x_kernel(const float* __restrict__ x) {
    int i = blockIdx.x * blockDim.x + threadIdx.x;
    if (i < NN * IND) g_xh[i] = __float2half(x[i]);
}
__global__ void convert_w_kernel(const float* __restrict__ Wl,
                                 const float* __restrict__ Wr) {
    int i = blockIdx.x * blockDim.x + threadIdx.x;
    if (i < IND * HC) {
        g_wh[0][i] = __float2half(Wl[i]);
        g_wh[1][i] = __float2half(Wr[i]);
    }
}

// ---------------- fused HMMA GEMM: xl AND xr in one kernel (R6 proven) ----------------
#define A_LD 72
#define B_LD 72
#define C_LD 72

__global__ __launch_bounds__(256) void gemm2_kernel() {
    __shared__ __align__(16) __half As[128 * A_LD];    // 18432 B (later reused as Cs)
    __shared__ __align__(16) __half Bs[2][IND * B_LD]; // 2 x 9216 B

    const int rb  = blockIdx.x * 128;
    const int cb  = blockIdx.y * 64;
    const int tid = threadIdx.x;
    const int wid = tid >> 5;
    const int wr  = (wid >> 1) * 32;
    const int wc  = (wid & 1) * 32;

#pragma unroll
    for (int i = 0; i < 4; i++) {
        int idx = tid + i * 256;
        int r = idx >> 3, c8 = idx & 7;
        uint4 v = make_uint4(0, 0, 0, 0);
        if (rb + r < NN)
            v = *(const uint4*)(g_xh + (size_t)(rb + r) * IND + c8 * 8);
        *(uint4*)(As + r * A_LD + c8 * 8) = v;
    }
#pragma unroll
    for (int i = 0; i < 4; i++) {
        int idx = tid + i * 256;
        int m = idx >> 9;
        int r = (idx >> 3) & 63, c8 = idx & 7;
        uint4 v = *(const uint4*)(g_wh[m] + (size_t)r * HC + cb + c8 * 8);
        *(uint4*)(Bs[m] + r * B_LD + c8 * 8) = v;
    }
    __syncthreads();

    wmma::fragment<wmma::accumulator, 16, 16, 16, float> acc[2][2][2];
#pragma unroll
    for (int m = 0; m < 2; m++)
#pragma unroll
        for (int i = 0; i < 2; i++)
#pragma unroll
            for (int j = 0; j < 2; j++) wmma::fill_fragment(acc[m][i][j], 0.0f);

#pragma unroll
    for (int k = 0; k < 4; k++) {
        wmma::fragment<wmma::matrix_a, 16, 16, 16, __half, wmma::row_major> a0, a1;
        wmma::load_matrix_sync(a0, As + (wr + 0)  * A_LD + k * 16, A_LD);
        wmma::load_matrix_sync(a1, As + (wr + 16) * A_LD + k * 16, A_LD);
#pragma unroll
        for (int m = 0; m < 2; m++) {
            wmma::fragment<wmma::matrix_b, 16, 16, 16, __half, wmma::row_major> b0, b1;
            wmma::load_matrix_sync(b0, Bs[m] + (k * 16) * B_LD + wc + 0,  B_LD);
            wmma::load_matrix_sync(b1, Bs[m] + (k * 16) * B_LD + wc + 16, B_LD);
            wmma::mma_sync(acc[m][0][0], a0, b0, acc[m][0][0]);
            wmma::mma_sync(acc[m][0][1], a0, b1, acc[m][0][1]);
            wmma::mma_sync(acc[m][1][0], a1, b0, acc[m][1][0]);
            wmma::mma_sync(acc[m][1][1], a1, b1, acc[m][1][1]);
        }
    }
    __syncthreads();

    __half* Cs = As;
#pragma unroll
    for (int m = 0; m < 2; m++) {
        __half* __restrict__ Y = m ? g_xr : g_xl;
#pragma unroll
        for (int i = 0; i < 2; i++)
#pragma unroll
            for (int j = 0; j < 2; j++) {
                wmma::fragment<wmma::accumulator, 16, 16, 16, __half> h;
#pragma unroll
                for (int t = 0; t < h.num_elements; t++)
                    h.x[t] = __float2half(acc[m][i][j].x[t]);
                wmma::store_matrix_sync(Cs + (wr + i * 16) * C_LD + wc + j * 16,
                                        h, C_LD, wmma::mem_row_major);
            }
        __syncthreads();
#pragma unroll
        for (int i = 0; i < 4; i++) {
            int idx = tid + i * 256;
            int r = idx >> 3, c8 = idx & 7;
            if (rb + r < NN) {
                uint4 v = *(const uint4*)(Cs + r * C_LD + c8 * 8);
                void* dst = Y + (size_t)(rb + r) * HC + cb + c8 * 8;
                if (m) stg_streaming_u4(dst, v);   // xr: read-once later
                else   *(uint4*)dst = v;           // xl: hot gather target
            }
        }
        __syncthreads();
    }
}

// ---------------- CSR build ----------------
__global__ void zero_count_kernel() {
    int i = blockIdx.x * blockDim.x + threadIdx.x;
    if (i < NN) g_count[i] = 0;
}

__global__ void hist_kernel(const int* __restrict__ dst) {
    int e = blockIdx.x * blockDim.x + threadIdx.x;
    if (e < NE) atomicAdd(&g_count[dst[e]], 1);
}

__global__ __launch_bounds__(SCAN_B) void scan_block_kernel() {
    __shared__ int sm[SCAN_B];
    int i = blockIdx.x * SCAN_B + threadIdx.x;
    int v = (i < NN) ? g_count[i] : 0;
    sm[threadIdx.x] = v;
    __syncthreads();
    for (int off = 1; off < SCAN_B; off <<= 1) {
        int t = (threadIdx.x >= off) ? sm[threadIdx.x - off] : 0;
        __syncthreads();
        sm[threadIdx.x] += t;
        __syncthreads();
    }
    if (i < NN) g_off[i] = sm[threadIdx.x] - v;
    if (threadIdx.x == SCAN_B - 1) g_bsum[blockIdx.x] = sm[SCAN_B - 1];
}

__global__ void scan_sums_kernel() {
    __shared__ int sm[128];
    int t = threadIdx.x;
    int v = (t < NBLK) ? g_bsum[t] : 0;
    sm[t] = v;
    __syncthreads();
    for (int off = 1; off < 128; off <<= 1) {
        int u = (t >= off) ? sm[t - off] : 0;
        __syncthreads();
        sm[t] += u;
        __syncthreads();
    }
    if (t < NBLK) g_bsum[t] = sm[t] - v;
}

__global__ __launch_bounds__(SCAN_B) void scan_add_kernel() {
    int i = blockIdx.x * SCAN_B + threadIdx.x;
    if (i < NN) {
        int o = g_off[i] + g_bsum[blockIdx.x];
        g_off[i] = o;
        g_cursor[i] = o;
    }
    if (i == 0) g_off[NN] = NE;
}

__global__ void scatter_kernel(const int* __restrict__ src,
                               const int* __restrict__ dst) {
    int e = blockIdx.x * blockDim.x + threadIdx.x;
    if (e < NE) {
        int d = dst[e];
        int pos = atomicAdd(&g_cursor[d], 1);
        g_srcs[pos] = src[e];
    }
}

// ---------------- fused node kernel: online softmax + aggregate ----------------
// TWO warps per destination node (R14 proven): half h owns 4 complete heads.
__device__ __forceinline__ float2 h2f(unsigned int u) {
    __half2 h = *reinterpret_cast<__half2*>(&u);
    return __half22float2(h);
}

__global__ __launch_bounds__(256) void node_kernel(const float* __restrict__ att,
                                                   const float* __restrict__ bias,
                                                   float* __restrict__ out) {
    int gw = (blockIdx.x * 256 + threadIdx.x) >> 5;   // global warp id
    int node = gw >> 1;
    int half = gw & 1;
    int lane = threadIdx.x & 31;
    if (node >= NN) return;
    const int base = half * 256 + lane * 8;   // 8 features per lane

    const u64 polL = policy_evict_last();
    const u64 polF = policy_evict_first();

    uint4 xu = ldg128_hint(g_xr + (size_t)node * HC + base, polF);
    float2 xr0 = h2f(xu.x), xr1 = h2f(xu.y), xr2 = h2f(xu.z), xr3 = h2f(xu.w);

    float4 at0 = *(const float4*)(att + base + 0);
    float4 at1 = *(const float4*)(att + base + 4);

    int p0 = g_off[node];
    int p1 = g_off[node + 1];

    float acc[8];
#pragma unroll
    for (int t = 0; t < 8; t++) acc[t] = 0.f;
    float denom = 0.f;

    auto edge = [&](const uint4& c) {
        float2 f0 = h2f(c.x), f1 = h2f(c.y), f2 = h2f(c.z), f3 = h2f(c.w);
        float sA = 0.f, sB = 0.f;
#define TERM(cv, xv, av) { float s_ = (cv) + (xv); sA = fmaf((av), s_, sA); sB = fmaf((av), fabsf(s_), sB); }
        TERM(f0.x, xr0.x, at0.x) TERM(f0.y, xr0.y, at0.y)
        TERM(f1.x, xr1.x, at0.z) TERM(f1.y, xr1.y, at0.w)
        TERM(f2.x, xr2.x, at1.x) TERM(f2.y, xr2.y, at1.y)
        TERM(f3.x, xr3.x, at1.z) TERM(f3.y, xr3.y, at1.w)
#undef TERM
        float part = fmaf(0.6f, sA, 0.4f * sB);   // == sum att*leaky02(s), 8 feats
        part += __shfl_xor_sync(0xffffffffu, part, 1);
        part += __shfl_xor_sync(0xffffffffu, part, 2);
        part += __shfl_xor_sync(0xffffffffu, part, 4);
        // max-free online softmax: |e| small, fp32 exp safe
        float ex = __expf(part);
        denom += ex;
        acc[0] = fmaf(ex, f0.x, acc[0]); acc[1] = fmaf(ex, f0.y, acc[1]);
        acc[2] = fmaf(ex, f1.x, acc[2]); acc[3] = fmaf(ex, f1.y, acc[3]);
        acc[4] = fmaf(ex, f2.x, acc[4]); acc[5] = fmaf(ex, f2.y, acc[5]);
        acc[6] = fmaf(ex, f3.x, acc[6]); acc[7] = fmaf(ex, f3.y, acc[7]);
    };

    if (p0 < p1) {
        int last = p1 - 1;
        int pB = (p0 + 1 < p1) ? (p0 + 1) : last;
        uint4 cA = ldg128_hint(g_xl + (size_t)__ldg(&g_srcs[p0]) * HC + base, polL);
        uint4 cB = ldg128_hint(g_xl + (size_t)__ldg(&g_srcs[pB]) * HC + base, polL);

        for (int p = p0; p < p1; p += 2) {
            // L2 prefetch 4-5 edges ahead
            int w0 = (p + 4 <= last) ? (p + 4) : last;
            int w1 = (p + 5 <= last) ? (p + 5) : last;
            const __half* pf0 = g_xl + (size_t)__ldg(&g_srcs[w0]) * HC + base;
            const __half* pf1 = g_xl + (size_t)__ldg(&g_srcs[w1]) * HC + base;
            asm volatile("prefetch.global.L2 [%0];" :: "l"(pf0));
            asm volatile("prefetch.global.L2 [%0];" :: "l"(pf1));

            // register prefetch of the next pair
            int q0 = (p + 2 <= last) ? (p + 2) : last;
            int q1 = (p + 3 <= last) ? (p + 3) : last;
            uint4 nA = ldg128_hint(g_xl + (size_t)__ldg(&g_srcs[q0]) * HC + base, polL);
            uint4 nB = ldg128_hint(g_xl + (size_t)__ldg(&g_srcs[q1]) * HC + base, polL);

            edge(cA);
            if (p + 1 < p1) edge(cB);

            cA = nA;
            cB = nB;
        }
    }

    float inv = 1.0f / (denom + 1e-16f);
    float4 b0 = *(const float4*)(bias + base + 0);
    float4 b1 = *(const float4*)(bias + base + 4);
    float* op = out + (size_t)node * HC + base;
    stg_streaming(op + 0, make_float4(acc[0] * inv + b0.x, acc[1] * inv + b0.y,
                                      acc[2] * inv + b0.z, acc[3] * inv + b0.w));
    stg_streaming(op + 4, make_float4(acc[4] * inv + b1.x, acc[5] * inv + b1.y,
                                      acc[6] * inv + b1.z, acc[7] * inv + b1.w));
}

// ---------------- stream/event singletons (created on first, uncaptured call) --------
static cudaStream_t make_stream() {
    cudaStream_t s; cudaStreamCreateWithFlags(&s, cudaStreamNonBlocking); return s;
}
static cudaEvent_t make_event() {
    cudaEvent_t e; cudaEventCreateWithFlags(&e, cudaEventDisableTiming); return e;
}

// ---------------- launch: two concurrent branches (GEMM || CSR), fork/join -----------
extern "C" void kernel_launch(void* const* d_in, const int* in_sizes, int n_in,
                              void* d_out, int out_size) {
    const float* x    = (const float*)d_in[0];
    const int*   ei   = (const int*)d_in[1];   // [2, NE] int32 (JAX x64 disabled)
    const float* W_l  = (const float*)d_in[2];
    const float* W_r  = (const float*)d_in[3];
    const float* att  = (const float*)d_in[4];
    const float* bias = (const float*)d_in[5];
    float*       out  = (float*)d_out;

    const int* src = ei;
    const int* dst = ei + NE;

    static cudaStream_t s2   = make_stream();
    static cudaEvent_t evFork = make_event();
    static cudaEvent_t evJoin = make_event();

    // fork: CSR branch on s2
    cudaEventRecord(evFork, 0);
    cudaStreamWaitEvent(s2, evFork, 0);
    zero_count_kernel<<<(NN + 255) / 256, 256, 0, s2>>>();
    hist_kernel<<<(NE + 255) / 256, 256, 0, s2>>>(dst);
    scan_block_kernel<<<NBLK, SCAN_B, 0, s2>>>();
    scan_sums_kernel<<<1, 128, 0, s2>>>();
    scan_add_kernel<<<NBLK, SCAN_B, 0, s2>>>();
    scatter_kernel<<<(NE + 255) / 256, 256, 0, s2>>>(src, dst);
    cudaEventRecord(evJoin, s2);

    // GEMM branch on the default stream
    convert_x_kernel<<<(NN * IND + 255) / 256, 256>>>(x);
    convert_w_kernel<<<(IND * HC + 255) / 256, 256>>>(W_l, W_r);
    dim3 ggrid((NN + 127) / 128, HC / 64);
    gemm2_kernel<<<ggrid, 256>>>();

    // join, then fused node phase (two warps per node)
    cudaStreamWaitEvent(0, evJoin, 0);
    node_kernel<<<(NN * 64 + 255) / 256, 256>>>(att, bias, out);
}

// round 16
// speedup vs baseline: 1.1907x; 1.0065x over previous
#include <cuda_runtime.h>
#include <cuda_fp16.h>
#include <mma.h>

using namespace nvcuda;

#define NN 100000
#define NE 800000
#define HC 512
#define IND 64
#define SCAN_B 1024
#define NBLK ((NN + SCAN_B - 1) / SCAN_B)   // 98

// ---------------- device scratch (no allocations allowed) ----------------
__device__ __half g_xl[(size_t)NN * HC];     // 102.4 MB
__device__ __half g_xr[(size_t)NN * HC];     // 102.4 MB
__device__ int    g_count[NN];
__device__ int    g_off[NN + 1];
__device__ int    g_cursor[NN];
__device__ int    g_srcs[NE];
__device__ int    g_bsum[NBLK];

typedef unsigned long long u64;

// ---------------- cache-policy helpers ----------------
__device__ __forceinline__ u64 policy_evict_last() {
    u64 pol; asm("createpolicy.fractional.L2::evict_last.b64 %0, 1.0;" : "=l"(pol));
    return pol;
}
__device__ __forceinline__ u64 policy_evict_first() {
    u64 pol; asm("createpolicy.fractional.L2::evict_first.b64 %0, 1.0;" : "=l"(pol));
    return pol;
}
__device__ __forceinline__ uint4 ldg128_hint(const void* p, u64 pol) {
    uint4 v;
    asm("ld.global.nc.L2::cache_hint.v4.b32 {%0,%1,%2,%3}, [%4], %5;"
        : "=r"(v.x), "=r"(v.y), "=r"(v.z), "=r"(v.w) : "l"(p), "l"(pol));
    return v;
}
__device__ __forceinline__ void stg_streaming(void* p, float4 v) {
    asm volatile("st.global.cs.v4.f32 [%0], {%1,%2,%3,%4};"
                 :: "l"(p), "f"(v.x), "f"(v.y), "f"(v.z), "f"(v.w));
}
__device__ __forceinline__ void stg_streaming_u4(void* p, uint4 v) {
    asm volatile("st.global.cs.v4.u32 [%0], {%1,%2,%3,%4};"
                 :: "l"(p), "r"(v.x), "r"(v.y), "r"(v.z), "r"(v.w));
}

// ---------------- fused HMMA GEMM: xl AND xr, fp32 inputs converted in-kernel --------
#define A_LD 72
#define B_LD 72
#define C_LD 72

__global__ __launch_bounds__(256) void gemm2_kernel(const float* __restrict__ x,
                                                    const float* __restrict__ Wl,
                                                    const float* __restrict__ Wr) {
    __shared__ __align__(16) __half As[128 * A_LD];    // 18432 B (later reused as Cs)
    __shared__ __align__(16) __half Bs[2][IND * B_LD]; // 2 x 9216 B

    const int rb  = blockIdx.x * 128;
    const int cb  = blockIdx.y * 64;
    const int tid = threadIdx.x;
    const int wid = tid >> 5;
    const int wr  = (wid >> 1) * 32;
    const int wc  = (wid & 1) * 32;

    // load A tile: 128x64 fp32 -> fp16; 2048 float4, 8 per thread
#pragma unroll
    for (int i = 0; i < 8; i++) {
        int idx = tid + i * 256;
        int r = idx >> 4, c4 = idx & 15;
        float4 v = make_float4(0.f, 0.f, 0.f, 0.f);
        if (rb + r < NN)
            v = *(const float4*)(x + (size_t)(rb + r) * IND + c4 * 4);
        __half2 h0 = __floats2half2_rn(v.x, v.y);
        __half2 h1 = __floats2half2_rn(v.z, v.w);
        *(__half2*)(As + r * A_LD + c4 * 4 + 0) = h0;
        *(__half2*)(As + r * A_LD + c4 * 4 + 2) = h1;
    }
    // load both B tiles: 2 x 64x64 fp32 -> fp16; 2048 float4, 8 per thread
#pragma unroll
    for (int i = 0; i < 8; i++) {
        int idx = tid + i * 256;
        int m = idx >> 10;
        int rem = idx & 1023;
        int r = rem >> 4, c4 = rem & 15;
        const float* W = m ? Wr : Wl;
        float4 v = *(const float4*)(W + (size_t)r * HC + cb + c4 * 4);
        __half2 h0 = __floats2half2_rn(v.x, v.y);
        __half2 h1 = __floats2half2_rn(v.z, v.w);
        *(__half2*)(Bs[m] + r * B_LD + c4 * 4 + 0) = h0;
        *(__half2*)(Bs[m] + r * B_LD + c4 * 4 + 2) = h1;
    }
    __syncthreads();

    wmma::fragment<wmma::accumulator, 16, 16, 16, float> acc[2][2][2];
#pragma unroll
    for (int m = 0; m < 2; m++)
#pragma unroll
        for (int i = 0; i < 2; i++)
#pragma unroll
            for (int j = 0; j < 2; j++) wmma::fill_fragment(acc[m][i][j], 0.0f);

#pragma unroll
    for (int k = 0; k < 4; k++) {
        wmma::fragment<wmma::matrix_a, 16, 16, 16, __half, wmma::row_major> a0, a1;
        wmma::load_matrix_sync(a0, As + (wr + 0)  * A_LD + k * 16, A_LD);
        wmma::load_matrix_sync(a1, As + (wr + 16) * A_LD + k * 16, A_LD);
#pragma unroll
        for (int m = 0; m < 2; m++) {
            wmma::fragment<wmma::matrix_b, 16, 16, 16, __half, wmma::row_major> b0, b1;
            wmma::load_matrix_sync(b0, Bs[m] + (k * 16) * B_LD + wc + 0,  B_LD);
            wmma::load_matrix_sync(b1, Bs[m] + (k * 16) * B_LD + wc + 16, B_LD);
            wmma::mma_sync(acc[m][0][0], a0, b0, acc[m][0][0]);
            wmma::mma_sync(acc[m][0][1], a0, b1, acc[m][0][1]);
            wmma::mma_sync(acc[m][1][0], a1, b0, acc[m][1][0]);
            wmma::mma_sync(acc[m][1][1], a1, b1, acc[m][1][1]);
        }
    }
    __syncthreads();

    __half* Cs = As;
#pragma unroll
    for (int m = 0; m < 2; m++) {
        __half* __restrict__ Y = m ? g_xr : g_xl;
#pragma unroll
        for (int i = 0; i < 2; i++)
#pragma unroll
            for (int j = 0; j < 2; j++) {
                wmma::fragment<wmma::accumulator, 16, 16, 16, __half> h;
#pragma unroll
                for (int t = 0; t < h.num_elements; t++)
                    h.x[t] = __float2half(acc[m][i][j].x[t]);
                wmma::store_matrix_sync(Cs + (wr + i * 16) * C_LD + wc + j * 16,
                                        h, C_LD, wmma::mem_row_major);
            }
        __syncthreads();
#pragma unroll
        for (int i = 0; i < 4; i++) {
            int idx = tid + i * 256;
            int r = idx >> 3, c8 = idx & 7;
            if (rb + r < NN) {
                uint4 v = *(const uint4*)(Cs + r * C_LD + c8 * 8);
                void* dst = Y + (size_t)(rb + r) * HC + cb + c8 * 8;
                if (m) stg_streaming_u4(dst, v);   // xr: read-once later
                else   *(uint4*)dst = v;           // xl: hot gather target
            }
        }
        __syncthreads();
    }
}

// ---------------- CSR build ----------------
__global__ void zero_count_kernel() {
    int i = blockIdx.x * blockDim.x + threadIdx.x;
    if (i < NN) g_count[i] = 0;
}

__global__ void hist_kernel(const int* __restrict__ dst) {
    int e = blockIdx.x * blockDim.x + threadIdx.x;
    if (e < NE) atomicAdd(&g_count[dst[e]], 1);
}

__global__ __launch_bounds__(SCAN_B) void scan_block_kernel() {
    __shared__ int sm[SCAN_B];
    int i = blockIdx.x * SCAN_B + threadIdx.x;
    int v = (i < NN) ? g_count[i] : 0;
    sm[threadIdx.x] = v;
    __syncthreads();
    for (int off = 1; off < SCAN_B; off <<= 1) {
        int t = (threadIdx.x >= off) ? sm[threadIdx.x - off] : 0;
        __syncthreads();
        sm[threadIdx.x] += t;
        __syncthreads();
    }
    if (i < NN) g_off[i] = sm[threadIdx.x] - v;
    if (threadIdx.x == SCAN_B - 1) g_bsum[blockIdx.x] = sm[SCAN_B - 1];
}

__global__ void scan_sums_kernel() {
    __shared__ int sm[128];
    int t = threadIdx.x;
    int v = (t < NBLK) ? g_bsum[t] : 0;
    sm[t] = v;
    __syncthreads();
    for (int off = 1; off < 128; off <<= 1) {
        int u = (t >= off) ? sm[t - off] : 0;
        __syncthreads();
        sm[t] += u;
        __syncthreads();
    }
    if (t < NBLK) g_bsum[t] = sm[t] - v;
}

__global__ __launch_bounds__(SCAN_B) void scan_add_kernel() {
    int i = blockIdx.x * SCAN_B + threadIdx.x;
    if (i < NN) {
        int o = g_off[i] + g_bsum[blockIdx.x];
        g_off[i] = o;
        g_cursor[i] = o;
    }
    if (i == 0) g_off[NN] = NE;
}

__global__ void scatter_kernel(const int* __restrict__ src,
                               const int* __restrict__ dst) {
    int e = blockIdx.x * blockDim.x + threadIdx.x;
    if (e < NE) {
        int d = dst[e];
        int pos = atomicAdd(&g_cursor[d], 1);
        g_srcs[pos] = src[e];
    }
}

// ---------------- fused node kernel: online softmax + aggregate ----------------
// TWO warps per destination node (R14 proven): half h owns 4 complete heads.
__device__ __forceinline__ float2 h2f(unsigned int u) {
    __half2 h = *reinterpret_cast<__half2*>(&u);
    return __half22float2(h);
}

__global__ __launch_bounds__(256) void node_kernel(const float* __restrict__ att,
                                                   const float* __restrict__ bias,
                                                   float* __restrict__ out) {
    int gw = (blockIdx.x * 256 + threadIdx.x) >> 5;   // global warp id
    int node = gw >> 1;
    int half = gw & 1;
    int lane = threadIdx.x & 31;
    if (node >= NN) return;
    const int base = half * 256 + lane * 8;   // 8 features per lane

    const u64 polL = policy_evict_last();
    const u64 polF = policy_evict_first();

    uint4 xu = ldg128_hint(g_xr + (size_t)node * HC + base, polF);
    float2 xr0 = h2f(xu.x), xr1 = h2f(xu.y), xr2 = h2f(xu.z), xr3 = h2f(xu.w);

    float4 at0 = *(const float4*)(att + base + 0);
    float4 at1 = *(const float4*)(att + base + 4);

    int p0 = g_off[node];
    int p1 = g_off[node + 1];

    float acc[8];
#pragma unroll
    for (int t = 0; t < 8; t++) acc[t] = 0.f;
    float denom = 0.f;

    auto edge = [&](const uint4& c) {
        float2 f0 = h2f(c.x), f1 = h2f(c.y), f2 = h2f(c.z), f3 = h2f(c.w);
        float sA = 0.f, sB = 0.f;
#define TERM(cv, xv, av) { float s_ = (cv) + (xv); sA = fmaf((av), s_, sA); sB = fmaf((av), fabsf(s_), sB); }
        TERM(f0.x, xr0.x, at0.x) TERM(f0.y, xr0.y, at0.y)
        TERM(f1.x, xr1.x, at0.z) TERM(f1.y, xr1.y, at0.w)
        TERM(f2.x, xr2.x, at1.x) TERM(f2.y, xr2.y, at1.y)
        TERM(f3.x, xr3.x, at1.z) TERM(f3.y, xr3.y, at1.w)
#undef TERM
        float part = fmaf(0.6f, sA, 0.4f * sB);   // == sum att*leaky02(s), 8 feats
        part += __shfl_xor_sync(0xffffffffu, part, 1);
        part += __shfl_xor_sync(0xffffffffu, part, 2);
        part += __shfl_xor_sync(0xffffffffu, part, 4);
        // max-free online softmax: |e| small, fp32 exp safe
        float ex = __expf(part);
        denom += ex;
        acc[0] = fmaf(ex, f0.x, acc[0]); acc[1] = fmaf(ex, f0.y, acc[1]);
        acc[2] = fmaf(ex, f1.x, acc[2]); acc[3] = fmaf(ex, f1.y, acc[3]);
        acc[4] = fmaf(ex, f2.x, acc[4]); acc[5] = fmaf(ex, f2.y, acc[5]);
        acc[6] = fmaf(ex, f3.x, acc[6]); acc[7] = fmaf(ex, f3.y, acc[7]);
    };

    if (p0 < p1) {
        int last = p1 - 1;
        int pB = (p0 + 1 < p1) ? (p0 + 1) : last;
        uint4 cA = ldg128_hint(g_xl + (size_t)__ldg(&g_srcs[p0]) * HC + base, polL);
        uint4 cB = ldg128_hint(g_xl + (size_t)__ldg(&g_srcs[pB]) * HC + base, polL);

        for (int p = p0; p < p1; p += 2) {
            // L2 prefetch 4-5 edges ahead
            int w0 = (p + 4 <= last) ? (p + 4) : last;
            int w1 = (p + 5 <= last) ? (p + 5) : last;
            const __half* pf0 = g_xl + (size_t)__ldg(&g_srcs[w0]) * HC + base;
            const __half* pf1 = g_xl + (size_t)__ldg(&g_srcs[w1]) * HC + base;
            asm volatile("prefetch.global.L2 [%0];" :: "l"(pf0));
            asm volatile("prefetch.global.L2 [%0];" :: "l"(pf1));

            // register prefetch of the next pair
            int q0 = (p + 2 <= last) ? (p + 2) : last;
            int q1 = (p + 3 <= last) ? (p + 3) : last;
            uint4 nA = ldg128_hint(g_xl + (size_t)__ldg(&g_srcs[q0]) * HC + base, polL);
            uint4 nB = ldg128_hint(g_xl + (size_t)__ldg(&g_srcs[q1]) * HC + base, polL);

            edge(cA);
            if (p + 1 < p1) edge(cB);

            cA = nA;
            cB = nB;
        }
    }

    float inv = 1.0f / (denom + 1e-16f);
    float4 b0 = *(const float4*)(bias + base + 0);
    float4 b1 = *(const float4*)(bias + base + 4);
    float* op = out + (size_t)node * HC + base;
    stg_streaming(op + 0, make_float4(acc[0] * inv + b0.x, acc[1] * inv + b0.y,
                                      acc[2] * inv + b0.z, acc[3] * inv + b0.w));
    stg_streaming(op + 4, make_float4(acc[4] * inv + b1.x, acc[5] * inv + b1.y,
                                      acc[6] * inv + b1.z, acc[7] * inv + b1.w));
}

// ---------------- stream/event singletons (created on first, uncaptured call) --------
static cudaStream_t make_stream() {
    cudaStream_t s; cudaStreamCreateWithFlags(&s, cudaStreamNonBlocking); return s;
}
static cudaEvent_t make_event() {
    cudaEvent_t e; cudaEventCreateWithFlags(&e, cudaEventDisableTiming); return e;
}

// ---------------- launch: two concurrent branches (GEMM || CSR), fork/join -----------
extern "C" void kernel_launch(void* const* d_in, const int* in_sizes, int n_in,
                              void* d_out, int out_size) {
    const float* x    = (const float*)d_in[0];
    const int*   ei   = (const int*)d_in[1];   // [2, NE] int32 (JAX x64 disabled)
    const float* W_l  = (const float*)d_in[2];
    const float* W_r  = (const float*)d_in[3];
    const float* att  = (const float*)d_in[4];
    const float* bias = (const float*)d_in[5];
    float*       out  = (float*)d_out;

    const int* src = ei;
    const int* dst = ei + NE;

    static cudaStream_t s2   = make_stream();
    static cudaEvent_t evFork = make_event();
    static cudaEvent_t evJoin = make_event();

    // fork: CSR branch on s2
    cudaEventRecord(evFork, 0);
    cudaStreamWaitEvent(s2, evFork, 0);
    zero_count_kernel<<<(NN + 255) / 256, 256, 0, s2>>>();
    hist_kernel<<<(NE + 255) / 256, 256, 0, s2>>>(dst);
    scan_block_kernel<<<NBLK, SCAN_B, 0, s2>>>();
    scan_sums_kernel<<<1, 128, 0, s2>>>();
    scan_add_kernel<<<NBLK, SCAN_B, 0, s2>>>();
    scatter_kernel<<<(NE + 255) / 256, 256, 0, s2>>>(src, dst);
    cudaEventRecord(evJoin, s2);

    // GEMM branch on the default stream (fp32 inputs, in-kernel fp16 convert)
    dim3 ggrid((NN + 127) / 128, HC / 64);
    gemm2_kernel<<<ggrid, 256>>>(x, W_l, W_r);

    // join, then fused node phase (two warps per node)
    cudaStreamWaitEvent(0, evJoin, 0);
    node_kernel<<<(NN * 64 + 255) / 256, 256>>>(att, bias, out);
}